// round 13
// baseline (speedup 1.0000x reference)
#include <cuda_runtime.h>
#include <cuda_fp16.h>
#include <cstdint>

#define N_NODES 100000
#define N_EDGES 1250000
#define NGRAPH  256
#define HID     64
#define IN_DIM  7

#define SCAN_E  1024
#define SCAN_B  ((N_NODES + SCAN_E - 1) / SCAN_E)   // 98

// ---------------- scratch (device globals; no allocation allowed) ----------
__device__ float g_dinv[N_NODES];
__device__ int   g_deg[N_NODES];        // invariant: zero at entry of each call
__device__ int   g_rowptr[N_NODES + 1];
__device__ int   g_cursor[N_NODES];
__device__ int   g_csr[N_EDGES];
__device__ unsigned long long g_lbstat[SCAN_B];   // lookback status (reset by k_deg)
__device__ __align__(16) __half g_bufH1[N_NODES * HID]; // fp16 dinv*H1
__device__ __align__(16) __half g_bufH2[N_NODES * HID]; // fp16 dinv*H2
__device__ __align__(16) float  g_bufB[N_NODES * HID];  // fp32 H3 (for pool)
__device__ __align__(16) float  g_x8[N_NODES * 8]; // dinv-scaled input, padded to 8

// ---------------- setup kernels -------------------------------------------
__global__ void k_deg(const int* __restrict__ ei) {
    int e = blockIdx.x * blockDim.x + threadIdx.x;
    if (e < N_EDGES) atomicAdd(&g_deg[ei[N_EDGES + e]], 1);
    if (blockIdx.x == 0 && threadIdx.x < SCAN_B) g_lbstat[threadIdx.x] = 0ull;
}

// single-pass scan with decoupled lookback + finalize:
// rowptr/cursor = exclusive prefix of deg; dinv = rsqrt(deg+1); x8 = x*dinv; deg = 0
__global__ void __launch_bounds__(256) k_scan(const float* __restrict__ x) {
    __shared__ int wraw[8], wscan[8];
    __shared__ int sprefix;
    int t = threadIdx.x, b = blockIdx.x;
    int base = b * SCAN_E + t * 4;
    int v0 = 0, v1 = 0, v2 = 0, v3 = 0;
    if (base + 0 < N_NODES) v0 = g_deg[base + 0];
    if (base + 1 < N_NODES) v1 = g_deg[base + 1];
    if (base + 2 < N_NODES) v2 = g_deg[base + 2];
    if (base + 3 < N_NODES) v3 = g_deg[base + 3];
    int ts = v0 + v1 + v2 + v3;
    int lane = t & 31, wid = t >> 5;
    int inc = ts;
    #pragma unroll
    for (int o = 1; o < 32; o <<= 1) {
        int y = __shfl_up_sync(0xffffffffu, inc, o);
        if (lane >= o) inc += y;
    }
    if (lane == 31) wraw[wid] = inc;
    __syncthreads();
    if (t < 8) {
        int w = wraw[t];
        #pragma unroll
        for (int o = 1; o < 8; o <<= 1) {
            int y = __shfl_up_sync(0xffu, w, o);
            if (t >= o) w += y;
        }
        wscan[t] = w;
    }
    __syncthreads();
    int blocksum = wscan[7];

    if (t == 0)
        atomicExch(&g_lbstat[b], (1ull << 62) | (unsigned long long)(unsigned)blocksum);
    if (wid == 0) {
        unsigned long long running = 0;
        int j = b - 1;
        while (j >= 0) {
            int idx = j - lane;
            unsigned flag = 1u;
            unsigned val = 0u;
            if (idx >= 0) {
                unsigned long long s;
                do { s = atomicAdd(&g_lbstat[idx], 0ull); } while ((s >> 62) == 0ull);
                flag = (unsigned)(s >> 62);
                val  = (unsigned)(s & 0xffffffffu);
            }
            unsigned pm = __ballot_sync(0xffffffffu, flag == 2u);
            int plane = pm ? (__ffs(pm) - 1) : 32;
            unsigned contrib = (plane < 32) ? ((lane <= plane) ? val : 0u) : val;
            #pragma unroll
            for (int o = 16; o; o >>= 1) contrib += __shfl_down_sync(0xffffffffu, contrib, o);
            contrib = __shfl_sync(0xffffffffu, contrib, 0);
            running += contrib;
            if (plane < 32) break;
            j -= 32;
        }
        if (lane == 0) {
            atomicExch(&g_lbstat[b],
                       (2ull << 62) | ((running + (unsigned long long)(unsigned)blocksum) & 0xffffffffu));
            sprefix = (int)running;
        }
    }
    __syncthreads();
    int ex = sprefix + (wid ? wscan[wid - 1] : 0) + (inc - ts);
    int exs[4] = {ex, ex + v0, ex + v0 + v1, ex + v0 + v1 + v2};
    int degs[4] = {v0, v1, v2, v3};
    #pragma unroll
    for (int j = 0; j < 4; j++) {
        int i = base + j;
        if (i < N_NODES) {
            g_rowptr[i] = exs[j];
            g_cursor[i] = exs[j];
            float dv = rsqrtf((float)(degs[j] + 1));
            g_dinv[i] = dv;
            float4 xa, xb;
            xa.x = x[i * IN_DIM + 0] * dv;
            xa.y = x[i * IN_DIM + 1] * dv;
            xa.z = x[i * IN_DIM + 2] * dv;
            xa.w = x[i * IN_DIM + 3] * dv;
            xb.x = x[i * IN_DIM + 4] * dv;
            xb.y = x[i * IN_DIM + 5] * dv;
            xb.z = x[i * IN_DIM + 6] * dv;
            xb.w = 0.f;
            *(float4*)&g_x8[i * 8]     = xa;
            *(float4*)&g_x8[i * 8 + 4] = xb;
            g_deg[i] = 0;                      // reset for next call
        }
    }
    if (b == 0 && t == 0) g_rowptr[N_NODES] = N_EDGES;
}

__global__ void k_scatter(const int* __restrict__ ei) {
    int e = blockIdx.x * blockDim.x + threadIdx.x;
    if (e < N_EDGES) {
        int d = ei[N_EDGES + e];
        int p = atomicAdd(&g_cursor[d], 1);
        g_csr[p] = ei[e];
    }
}

// ---------------- layer 1: fused 8-dim aggregate + 7->64 GEMM + relu -------
// warp per node (R8-measured agg); outputs fp16 dinv*H1
__global__ void __launch_bounds__(256) k_l1(const float* __restrict__ W1,
                                            const float* __restrict__ b1) {
    __shared__ float sW[IN_DIM * HID];
    __shared__ float sB[HID];
    int t = threadIdx.x;
    for (int i = t; i < IN_DIM * HID; i += 256) sW[i] = W1[i];
    if (t < HID) sB[t] = b1[t];
    __syncthreads();
    int w = blockIdx.x * 8 + (t >> 5);
    if (w >= N_NODES) return;
    int lane = t & 31;
    int grp = lane >> 3, dim = lane & 7;
    float acc  = (grp == 0) ? g_x8[w * 8 + dim] : 0.f;   // self term
    float acc2 = 0.f;
    int beg = g_rowptr[w], end = g_rowptr[w + 1];
    int e = beg + grp;
    for (; e + 4 < end; e += 8) {                         // 2 edges per grp in flight
        int u0 = g_csr[e], u1 = g_csr[e + 4];
        acc  += g_x8[u0 * 8 + dim];
        acc2 += g_x8[u1 * 8 + dim];
    }
    if (e < end) acc += g_x8[g_csr[e] * 8 + dim];
    acc += acc2;
    __syncwarp();
    acc += __shfl_down_sync(0xffffffffu, acc, 16);
    acc += __shfl_down_sync(0xffffffffu, acc, 8);
    float dv = g_dinv[w];
    float a7 = acc * dv;                                  // valid in lanes 0..7
    float a0 = sB[lane], a1 = sB[32 + lane];
    #pragma unroll
    for (int k = 0; k < IN_DIM; k++) {
        float xk = __shfl_sync(0xffffffffu, a7, k);
        a0 += xk * sW[k * HID + lane];
        a1 += xk * sW[k * HID + 32 + lane];
    }
    g_bufH1[w * HID + lane]      = __float2half(fmaxf(a0, 0.f) * dv);
    g_bufH1[w * HID + 32 + lane] = __float2half(fmaxf(a1, 0.f) * dv);
}

// ---------------- fused 64-dim layer: agg(fp16 g') -> tf32 MMA -> out ------
__device__ __forceinline__ uint32_t f2tf32(float f) {
    uint32_t u;
    asm("cvt.rna.tf32.f32 %0, %1;" : "=r"(u) : "f"(f));
    return u;
}

__device__ __forceinline__ void mma_tf32(float* c,
                                         uint32_t a0, uint32_t a1, uint32_t a2, uint32_t a3,
                                         uint32_t b0, uint32_t b1) {
    asm volatile(
        "mma.sync.aligned.m16n8k8.row.col.f32.tf32.tf32.f32 "
        "{%0,%1,%2,%3}, {%4,%5,%6,%7}, {%8,%9}, {%0,%1,%2,%3};"
        : "+f"(c[0]), "+f"(c[1]), "+f"(c[2]), "+f"(c[3])
        : "r"(a0), "r"(a1), "r"(a2), "r"(a3), "r"(b0), "r"(b1));
}

__device__ __forceinline__ void h4acc(float4& a, uint2 v) {
    __half2 h0 = *(__half2*)&v.x;
    __half2 h1 = *(__half2*)&v.y;
    float2 f0 = __half22float2(h0);
    float2 f1 = __half22float2(h1);
    a.x += f0.x; a.y += f0.y; a.z += f1.x; a.w += f1.y;
}

// mode 1: in g_bufH1, relu, out fp16 dinv*H2 -> g_bufH2
// mode 0: in g_bufH2, no relu, out fp32 H3 -> g_bufB
__global__ void __launch_bounds__(128) k_layer(const float* __restrict__ W,
                                               const float* __restrict__ bias,
                                               int mode) {
    __shared__ uint32_t sA[64][68];   // tf32 aggregated features [m][k]
    __shared__ uint32_t sWt[64][68];  // tf32 W^T [n][k]
    __shared__ float sB[HID];
    int t = threadIdx.x;
    int nb = blockIdx.x * 64;
    const float4* W4 = (const float4*)W;
    #pragma unroll
    for (int i = t; i < 1024; i += 128) {        // W[k][n quad] -> sWt[n][k]
        float4 v = W4[i];
        int k = i >> 4, n4 = (i & 15) * 4;
        sWt[n4 + 0][k] = f2tf32(v.x);
        sWt[n4 + 1][k] = f2tf32(v.y);
        sWt[n4 + 2][k] = f2tf32(v.z);
        sWt[n4 + 3][k] = f2tf32(v.w);
    }
    if (t < HID) sB[t] = bias[t];

    int lane = t & 31, warp = t >> 5;
    int half = lane >> 4, sub = lane & 15;
    const uint2* H = mode ? (const uint2*)g_bufH1 : (const uint2*)g_bufH2;

    // each warp aggregates its own 16 M-rows into sA (no cross-warp dependency)
    for (int s = 0; s < 16; s++) {
        int m = warp * 16 + s;
        int v = nb + m;
        if (v < N_NODES) {
            float4 acc = make_float4(0.f, 0.f, 0.f, 0.f);
            if (half == 0) h4acc(acc, H[v * 16 + sub]);   // self term
            int beg = g_rowptr[v], end = g_rowptr[v + 1];
            int e = beg + half;
            for (; e + 6 < end; e += 8) {                  // 4 edges per half in flight
                int u0 = g_csr[e],     u1 = g_csr[e + 2];
                int u2 = g_csr[e + 4], u3 = g_csr[e + 6];
                uint2 x0 = H[u0 * 16 + sub];
                uint2 x1 = H[u1 * 16 + sub];
                uint2 x2 = H[u2 * 16 + sub];
                uint2 x3 = H[u3 * 16 + sub];
                h4acc(acc, x0); h4acc(acc, x1); h4acc(acc, x2); h4acc(acc, x3);
            }
            for (; e < end; e += 2) h4acc(acc, H[g_csr[e] * 16 + sub]);
            __syncwarp();
            acc.x += __shfl_down_sync(0xffffffffu, acc.x, 16);
            acc.y += __shfl_down_sync(0xffffffffu, acc.y, 16);
            acc.z += __shfl_down_sync(0xffffffffu, acc.z, 16);
            acc.w += __shfl_down_sync(0xffffffffu, acc.w, 16);
            if (half == 0) {
                float dv = g_dinv[v];
                uint4 pk;
                pk.x = f2tf32(acc.x * dv);
                pk.y = f2tf32(acc.y * dv);
                pk.z = f2tf32(acc.z * dv);
                pk.w = f2tf32(acc.w * dv);
                *(uint4*)&sA[m][sub * 4] = pk;
            }
        } else if (half == 0) {
            *(uint4*)&sA[m][sub * 4] = make_uint4(0u, 0u, 0u, 0u);
        }
    }
    __syncthreads();   // sWt/sB visibility (sA rows are same-warp)

    int g   = lane >> 2;        // groupID 0..7
    int tid = lane & 3;         // 0..3
    int m0  = warp * 16;

    float acc[8][4] = {};
    #pragma unroll
    for (int ks = 0; ks < 8; ks++) {
        int k0 = ks * 8;
        uint32_t a0 = sA[m0 + g][k0 + tid];
        uint32_t a1 = sA[m0 + g + 8][k0 + tid];
        uint32_t a2 = sA[m0 + g][k0 + tid + 4];
        uint32_t a3 = sA[m0 + g + 8][k0 + tid + 4];
        #pragma unroll
        for (int n = 0; n < 8; n++) {
            uint32_t b0 = sWt[n * 8 + g][k0 + tid];
            uint32_t b1 = sWt[n * 8 + g][k0 + tid + 4];
            mma_tf32(acc[n], a0, a1, a2, a3, b0, b1);
        }
    }

    // epilogue: rows g, g+8; cols 2*tid, 2*tid+1 per n-tile
    int node0 = nb + m0 + g;
    int node1 = node0 + 8;
    float s0 = (node0 < N_NODES) ? g_dinv[node0] : 0.f;
    float s1 = (node1 < N_NODES) ? g_dinv[node1] : 0.f;
    #pragma unroll
    for (int n = 0; n < 8; n++) {
        int col = n * 8 + tid * 2;
        float c0 = acc[n][0] + sB[col], c1 = acc[n][1] + sB[col + 1];
        float c2 = acc[n][2] + sB[col], c3 = acc[n][3] + sB[col + 1];
        if (mode) {
            c0 = fmaxf(c0, 0.f); c1 = fmaxf(c1, 0.f);
            c2 = fmaxf(c2, 0.f); c3 = fmaxf(c3, 0.f);
            if (node0 < N_NODES)
                *(__half2*)&g_bufH2[node0 * HID + col] = __floats2half2_rn(c0 * s0, c1 * s0);
            if (node1 < N_NODES)
                *(__half2*)&g_bufH2[node1 * HID + col] = __floats2half2_rn(c2 * s1, c3 * s1);
        } else {
            if (node0 < N_NODES)
                *(float2*)&g_bufB[node0 * HID + col] = make_float2(c0, c1);
            if (node1 < N_NODES)
                *(float2*)&g_bufB[node1 * HID + col] = make_float2(c2, c3);
        }
    }
}

// pooling + final linear over bufB; graph ranges via binary search on sorted batch
__global__ void k_pool(const int* __restrict__ batch,
                       const float* __restrict__ Wl, const float* __restrict__ bl,
                       float* __restrict__ outp) {
    __shared__ float sh[256];
    int gph = blockIdx.x;
    int t = threadIdx.x;
    int lo = 0, hi = N_NODES;
    while (lo < hi) { int mid = (lo + hi) >> 1; if (batch[mid] < gph) lo = mid + 1; else hi = mid; }
    int s = lo;
    hi = N_NODES;
    while (lo < hi) { int mid = (lo + hi) >> 1; if (batch[mid] < gph + 1) lo = mid + 1; else hi = mid; }
    int c = lo - s;
    int d = t & 63, grp = t >> 6;
    float acc = 0.f;
    for (int i = grp; i < c; i += 4) acc += g_bufB[(s + i) * HID + d];
    sh[t] = acc;
    __syncthreads();
    if (t < 64) {
        float p = sh[t] + sh[64 + t] + sh[128 + t] + sh[192 + t];
        p *= 1.0f / fmaxf((float)c, 1.0f);
        sh[t] = p;
    }
    __syncthreads();
    if (t < 2) {
        float o = bl[t];
        #pragma unroll 8
        for (int dd = 0; dd < HID; dd++) o += sh[dd] * Wl[dd * 2 + t];
        outp[gph * 2 + t] = o;
    }
}

// ---------------- launch ---------------------------------------------------
extern "C" void kernel_launch(void* const* d_in, const int* in_sizes, int n_in,
                              void* d_out, int out_size) {
    const float* x     = (const float*)d_in[0];
    const int*   ei    = (const int*)d_in[1];    // int64 in reference -> int32 in harness
    const int*   batch = (const int*)d_in[2];
    const float* W1 = (const float*)d_in[3];
    const float* b1 = (const float*)d_in[4];
    const float* W2 = (const float*)d_in[5];
    const float* b2 = (const float*)d_in[6];
    const float* W3 = (const float*)d_in[7];
    const float* b3 = (const float*)d_in[8];
    const float* Wl = (const float*)d_in[9];
    const float* bl = (const float*)d_in[10];
    float* out = (float*)d_out;

    const int TB = 256;
    int nbE = (N_EDGES + TB - 1) / TB;                 // 4883
    int nbWarp = (N_NODES + 7) / 8;                    // 12500
    int nbTile = (N_NODES + 63) / 64;                  // 1563

    // CSR build + dinv + scaled input (3 launches)
    k_deg<<<nbE, TB>>>(ei);
    k_scan<<<SCAN_B, 256>>>(x);
    k_scatter<<<nbE, TB>>>(ei);

    // layer 1 (agg7 + GEMM + relu, fp16 out)
    k_l1<<<nbWarp, 256>>>(W1, b1);
    // layer 2: fused agg + GEMM + relu (fp16 out)
    k_layer<<<nbTile, 128>>>(W2, b2, 1);
    // layer 3: fused agg + GEMM (fp32 out)
    k_layer<<<nbTile, 128>>>(W3, b3, 0);

    // pooling + classifier
    k_pool<<<NGRAPH, 256>>>(batch, Wl, bl, out);
}

// round 16
// speedup vs baseline: 1.3154x; 1.3154x over previous
#include <cuda_runtime.h>
#include <cuda_fp16.h>
#include <cstdint>

#define N_NODES 100000
#define N_EDGES 1250000
#define NGRAPH  256
#define HID     64
#define IN_DIM  7

#define SCAN_E  1024
#define SCAN_B  ((N_NODES + SCAN_E - 1) / SCAN_E)   // 98

// ---------------- scratch (device globals; no allocation allowed) ----------
__device__ float g_dinv[N_NODES];
__device__ int   g_deg[N_NODES];        // invariant: zero at entry of each call
__device__ int   g_rowptr[N_NODES + 1];
__device__ int   g_cursor[N_NODES];
__device__ int   g_csr[N_EDGES];
__device__ unsigned long long g_lbstat[SCAN_B];   // lookback status (reset by k_deg)
__device__ __align__(16) __half g_bufH[N_NODES * HID];  // fp16 GEMM output g
__device__ __align__(16) float  g_bufB[N_NODES * HID];  // fp32 hidden H
__device__ __align__(16) __half g_xh[N_NODES * 8];      // fp16 dinv-scaled input (16B/row)

// ---------------- setup kernels -------------------------------------------
__global__ void k_deg(const int* __restrict__ ei) {
    int e = blockIdx.x * blockDim.x + threadIdx.x;
    if (e < N_EDGES) atomicAdd(&g_deg[ei[N_EDGES + e]], 1);
    if (blockIdx.x == 0 && threadIdx.x < SCAN_B) g_lbstat[threadIdx.x] = 0ull;
}

// single-pass scan with decoupled lookback + finalize:
// rowptr/cursor = exclusive prefix of deg; dinv = rsqrt(deg+1); xh = fp16(x*dinv); deg = 0
__global__ void __launch_bounds__(256) k_scan(const float* __restrict__ x) {
    __shared__ int wraw[8], wscan[8];
    __shared__ int sprefix;
    int t = threadIdx.x, b = blockIdx.x;
    int base = b * SCAN_E + t * 4;
    int v0 = 0, v1 = 0, v2 = 0, v3 = 0;
    if (base + 0 < N_NODES) v0 = g_deg[base + 0];
    if (base + 1 < N_NODES) v1 = g_deg[base + 1];
    if (base + 2 < N_NODES) v2 = g_deg[base + 2];
    if (base + 3 < N_NODES) v3 = g_deg[base + 3];
    int ts = v0 + v1 + v2 + v3;
    int lane = t & 31, wid = t >> 5;
    int inc = ts;
    #pragma unroll
    for (int o = 1; o < 32; o <<= 1) {
        int y = __shfl_up_sync(0xffffffffu, inc, o);
        if (lane >= o) inc += y;
    }
    if (lane == 31) wraw[wid] = inc;
    __syncthreads();
    if (t < 8) {
        int w = wraw[t];
        #pragma unroll
        for (int o = 1; o < 8; o <<= 1) {
            int y = __shfl_up_sync(0xffu, w, o);
            if (t >= o) w += y;
        }
        wscan[t] = w;
    }
    __syncthreads();
    int blocksum = wscan[7];

    if (t == 0)
        atomicExch(&g_lbstat[b], (1ull << 62) | (unsigned long long)(unsigned)blocksum);
    if (wid == 0) {
        unsigned long long running = 0;
        int j = b - 1;
        while (j >= 0) {
            int idx = j - lane;
            unsigned flag = 1u;
            unsigned val = 0u;
            if (idx >= 0) {
                unsigned long long s;
                do { s = atomicAdd(&g_lbstat[idx], 0ull); } while ((s >> 62) == 0ull);
                flag = (unsigned)(s >> 62);
                val  = (unsigned)(s & 0xffffffffu);
            }
            unsigned pm = __ballot_sync(0xffffffffu, flag == 2u);
            int plane = pm ? (__ffs(pm) - 1) : 32;
            unsigned contrib = (plane < 32) ? ((lane <= plane) ? val : 0u) : val;
            #pragma unroll
            for (int o = 16; o; o >>= 1) contrib += __shfl_down_sync(0xffffffffu, contrib, o);
            contrib = __shfl_sync(0xffffffffu, contrib, 0);
            running += contrib;
            if (plane < 32) break;
            j -= 32;
        }
        if (lane == 0) {
            atomicExch(&g_lbstat[b],
                       (2ull << 62) | ((running + (unsigned long long)(unsigned)blocksum) & 0xffffffffu));
            sprefix = (int)running;
        }
    }
    __syncthreads();
    int ex = sprefix + (wid ? wscan[wid - 1] : 0) + (inc - ts);
    int exs[4] = {ex, ex + v0, ex + v0 + v1, ex + v0 + v1 + v2};
    int degs[4] = {v0, v1, v2, v3};
    #pragma unroll
    for (int j = 0; j < 4; j++) {
        int i = base + j;
        if (i < N_NODES) {
            g_rowptr[i] = exs[j];
            g_cursor[i] = exs[j];
            float dv = rsqrtf((float)(degs[j] + 1));
            g_dinv[i] = dv;
            __half2 h0 = __floats2half2_rn(x[i * IN_DIM + 0] * dv, x[i * IN_DIM + 1] * dv);
            __half2 h1 = __floats2half2_rn(x[i * IN_DIM + 2] * dv, x[i * IN_DIM + 3] * dv);
            __half2 h2 = __floats2half2_rn(x[i * IN_DIM + 4] * dv, x[i * IN_DIM + 5] * dv);
            __half2 h3 = __floats2half2_rn(x[i * IN_DIM + 6] * dv, 0.f);
            uint4 pk;
            pk.x = *(uint32_t*)&h0; pk.y = *(uint32_t*)&h1;
            pk.z = *(uint32_t*)&h2; pk.w = *(uint32_t*)&h3;
            *(uint4*)&g_xh[i * 8] = pk;
            g_deg[i] = 0;                      // reset for next call
        }
    }
    if (b == 0 && t == 0) g_rowptr[N_NODES] = N_EDGES;
}

__global__ void k_scatter(const int* __restrict__ ei) {
    int e = blockIdx.x * blockDim.x + threadIdx.x;
    if (e < N_EDGES) {
        int d = ei[N_EDGES + e];
        int p = atomicAdd(&g_cursor[d], 1);
        g_csr[p] = ei[e];
    }
}

// ---------------- layer 1: fused fp16 aggregate + 7->64 GEMM + relu --------
// warp per node; 4 lanes/edge x uint (2 halves) -> 8 edge-groups, 16 edges in
// flight with unroll 2; 1 line per edge (16B row).
__global__ void __launch_bounds__(256) k_l1(const float* __restrict__ W1,
                                            const float* __restrict__ b1) {
    __shared__ float sW[IN_DIM * HID];
    __shared__ float sB[HID];
    int t = threadIdx.x;
    for (int i = t; i < IN_DIM * HID; i += 256) sW[i] = W1[i];
    if (t < HID) sB[t] = b1[t];
    __syncthreads();
    int w = blockIdx.x * 8 + (t >> 5);
    if (w >= N_NODES) return;
    int lane = t & 31;
    int g = lane >> 2, q = lane & 3;           // group 0..7, dim-pair q -> dims 2q,2q+1
    const uint32_t* X = (const uint32_t*)g_xh; // row stride = 4 uints
    float ax = 0.f, ay = 0.f, ax2 = 0.f, ay2 = 0.f;
    if (g == 0) {                               // self term
        uint32_t v = X[w * 4 + q];
        float2 f = __half22float2(*(__half2*)&v);
        ax += f.x; ay += f.y;
    }
    int beg = g_rowptr[w], end = g_rowptr[w + 1];
    int e = beg + g;
    for (; e + 8 < end; e += 16) {              // 2 edges per group in flight
        int u0 = g_csr[e], u1 = g_csr[e + 8];
        uint32_t v0 = X[u0 * 4 + q];
        uint32_t v1 = X[u1 * 4 + q];
        float2 f0 = __half22float2(*(__half2*)&v0);
        float2 f1 = __half22float2(*(__half2*)&v1);
        ax += f0.x; ay += f0.y;
        ax2 += f1.x; ay2 += f1.y;
    }
    if (e < end) {
        uint32_t v = X[g_csr[e] * 4 + q];
        float2 f = __half22float2(*(__half2*)&v);
        ax += f.x; ay += f.y;
    }
    ax += ax2; ay += ay2;
    __syncwarp();
    #pragma unroll
    for (int o = 16; o >= 4; o >>= 1) {         // reduce across groups (stride 4 lanes)
        ax += __shfl_down_sync(0xffffffffu, ax, o);
        ay += __shfl_down_sync(0xffffffffu, ay, o);
    }
    float dv = g_dinv[w];
    ax *= dv; ay *= dv;                         // lanes 0..3: dims 2q (ax), 2q+1 (ay)
    float a0 = sB[lane], a1 = sB[32 + lane];
    {
        float xk;
        xk = __shfl_sync(0xffffffffu, ax, 0);   // dim 0
        a0 += xk * sW[0 * HID + lane];  a1 += xk * sW[0 * HID + 32 + lane];
        xk = __shfl_sync(0xffffffffu, ay, 0);   // dim 1
        a0 += xk * sW[1 * HID + lane];  a1 += xk * sW[1 * HID + 32 + lane];
        xk = __shfl_sync(0xffffffffu, ax, 1);   // dim 2
        a0 += xk * sW[2 * HID + lane];  a1 += xk * sW[2 * HID + 32 + lane];
        xk = __shfl_sync(0xffffffffu, ay, 1);   // dim 3
        a0 += xk * sW[3 * HID + lane];  a1 += xk * sW[3 * HID + 32 + lane];
        xk = __shfl_sync(0xffffffffu, ax, 2);   // dim 4
        a0 += xk * sW[4 * HID + lane];  a1 += xk * sW[4 * HID + 32 + lane];
        xk = __shfl_sync(0xffffffffu, ay, 2);   // dim 5
        a0 += xk * sW[5 * HID + lane];  a1 += xk * sW[5 * HID + 32 + lane];
        xk = __shfl_sync(0xffffffffu, ax, 3);   // dim 6
        a0 += xk * sW[6 * HID + lane];  a1 += xk * sW[6 * HID + 32 + lane];
    }
    g_bufB[w * HID + lane]      = fmaxf(a0, 0.f);
    g_bufB[w * HID + 32 + lane] = fmaxf(a1, 0.f);
}

// ---------------- 64-dim layers --------------------------------------------
__device__ __forceinline__ uint32_t f2tf32(float f) {
    uint32_t u;
    asm("cvt.rna.tf32.f32 %0, %1;" : "=r"(u) : "f"(f));
    return u;
}

__device__ __forceinline__ void mma_tf32(float* c,
                                         uint32_t a0, uint32_t a1, uint32_t a2, uint32_t a3,
                                         uint32_t b0, uint32_t b1) {
    asm volatile(
        "mma.sync.aligned.m16n8k8.row.col.f32.tf32.tf32.f32 "
        "{%0,%1,%2,%3}, {%4,%5,%6,%7}, {%8,%9}, {%0,%1,%2,%3};"
        : "+f"(c[0]), "+f"(c[1]), "+f"(c[2]), "+f"(c[3])
        : "r"(a0), "r"(a1), "r"(a2), "r"(a3), "r"(b0), "r"(b1));
}

// GEMM tile via tf32 mma: bufH = (half) dinv[v] * (bufB[v] @ W); 64 nodes/block.
__global__ void __launch_bounds__(128) k_xw64(const float* __restrict__ W) {
    __shared__ uint32_t sA[64][68];   // tf32 bits of input  [m][k]
    __shared__ uint32_t sWt[64][68];  // tf32 bits of W^T    [n][k]
    int t = threadIdx.x;
    int nb = blockIdx.x * 64;
    const float4* W4 = (const float4*)W;
    #pragma unroll
    for (int i = t; i < 1024; i += 128) {        // W[k][n quad] -> sWt[n][k]
        float4 v = W4[i];
        int k = i >> 4, n4 = (i & 15) * 4;
        sWt[n4 + 0][k] = f2tf32(v.x);
        sWt[n4 + 1][k] = f2tf32(v.y);
        sWt[n4 + 2][k] = f2tf32(v.z);
        sWt[n4 + 3][k] = f2tf32(v.w);
    }
    const float4* B4 = (const float4*)g_bufB;
    #pragma unroll
    for (int i = t; i < 1024; i += 128) {        // bufB[node][k quad] -> sA[m][k]
        int m = i >> 4, k4 = (i & 15) * 4;
        int node = nb + m;
        float4 v = (node < N_NODES) ? B4[node * 16 + (i & 15)] : make_float4(0.f, 0.f, 0.f, 0.f);
        sA[m][k4 + 0] = f2tf32(v.x);
        sA[m][k4 + 1] = f2tf32(v.y);
        sA[m][k4 + 2] = f2tf32(v.z);
        sA[m][k4 + 3] = f2tf32(v.w);
    }
    __syncthreads();

    int lane = t & 31, warp = t >> 5;
    int g   = lane >> 2;        // groupID 0..7
    int tid = lane & 3;         // 0..3
    int m0  = warp * 16;

    float acc[8][4] = {};
    #pragma unroll
    for (int ks = 0; ks < 8; ks++) {
        int k0 = ks * 8;
        uint32_t a0 = sA[m0 + g][k0 + tid];
        uint32_t a1 = sA[m0 + g + 8][k0 + tid];
        uint32_t a2 = sA[m0 + g][k0 + tid + 4];
        uint32_t a3 = sA[m0 + g + 8][k0 + tid + 4];
        #pragma unroll
        for (int n = 0; n < 8; n++) {
            uint32_t b0 = sWt[n * 8 + g][k0 + tid];
            uint32_t b1 = sWt[n * 8 + g][k0 + tid + 4];
            mma_tf32(acc[n], a0, a1, a2, a3, b0, b1);
        }
    }

    // epilogue: rows g, g+8; cols 2*tid, 2*tid+1 per n-tile -> fp16 pairs
    int node0 = nb + m0 + g;
    int node1 = node0 + 8;
    float s0 = (node0 < N_NODES) ? g_dinv[node0] : 0.f;
    float s1 = (node1 < N_NODES) ? g_dinv[node1] : 0.f;
    #pragma unroll
    for (int n = 0; n < 8; n++) {
        int col = n * 8 + tid * 2;
        if (node0 < N_NODES) {
            __half2 hv = __floats2half2_rn(acc[n][0] * s0, acc[n][1] * s0);
            *(__half2*)&g_bufH[node0 * HID + col] = hv;
        }
        if (node1 < N_NODES) {
            __half2 hv = __floats2half2_rn(acc[n][2] * s1, acc[n][3] * s1);
            *(__half2*)&g_bufH[node1 * HID + col] = hv;
        }
    }
}

// aggregation (fp16 gather, fp32 accum):
// bufB[v] = act( dinv[v]*(bufH[v] + sum_{CSR[v]} bufH[u]) + bias )
// half-warp x uint2 (R12-measured); halves split edges stride-2; unroll 4.
__device__ __forceinline__ void h4acc(float4& a, uint2 v) {
    __half2 h0 = *(__half2*)&v.x;
    __half2 h1 = *(__half2*)&v.y;
    float2 f0 = __half22float2(h0);
    float2 f1 = __half22float2(h1);
    a.x += f0.x; a.y += f0.y; a.z += f1.x; a.w += f1.y;
}

__global__ void __launch_bounds__(256) k_aggh(const float* __restrict__ bias, int do_relu) {
    int w = (blockIdx.x * blockDim.x + threadIdx.x) >> 5;
    if (w >= N_NODES) return;
    int lane = threadIdx.x & 31;
    int half = lane >> 4, sub = lane & 15;    // sub covers dims 4*sub .. 4*sub+3
    const uint2* H = (const uint2*)g_bufH;    // row stride = 16 uint2
    float4 acc = make_float4(0.f, 0.f, 0.f, 0.f);
    if (half == 0) h4acc(acc, H[w * 16 + sub]);           // self term once
    int beg = g_rowptr[w], end = g_rowptr[w + 1];
    int e = beg + half;
    for (; e + 6 < end; e += 8) {                          // 4 edges per half in flight
        int u0 = g_csr[e],     u1 = g_csr[e + 2];
        int u2 = g_csr[e + 4], u3 = g_csr[e + 6];
        uint2 v0 = H[u0 * 16 + sub];
        uint2 v1 = H[u1 * 16 + sub];
        uint2 v2 = H[u2 * 16 + sub];
        uint2 v3 = H[u3 * 16 + sub];
        h4acc(acc, v0); h4acc(acc, v1); h4acc(acc, v2); h4acc(acc, v3);
    }
    for (; e < end; e += 2) h4acc(acc, H[g_csr[e] * 16 + sub]);
    __syncwarp();
    acc.x += __shfl_down_sync(0xffffffffu, acc.x, 16);
    acc.y += __shfl_down_sync(0xffffffffu, acc.y, 16);
    acc.z += __shfl_down_sync(0xffffffffu, acc.z, 16);
    acc.w += __shfl_down_sync(0xffffffffu, acc.w, 16);
    if (half == 0) {
        float s = g_dinv[w];
        float4 bb = ((const float4*)bias)[sub];
        float4 r;
        r.x = acc.x * s + bb.x; r.y = acc.y * s + bb.y;
        r.z = acc.z * s + bb.z; r.w = acc.w * s + bb.w;
        if (do_relu) {
            r.x = fmaxf(r.x, 0.f); r.y = fmaxf(r.y, 0.f);
            r.z = fmaxf(r.z, 0.f); r.w = fmaxf(r.w, 0.f);
        }
        ((float4*)g_bufB)[w * 16 + sub] = r;
    }
}

// pooling + final linear over bufB; graph ranges via binary search on sorted batch
__global__ void k_pool(const int* __restrict__ batch,
                       const float* __restrict__ Wl, const float* __restrict__ bl,
                       float* __restrict__ outp) {
    __shared__ float sh[256];
    int gph = blockIdx.x;
    int t = threadIdx.x;
    int lo = 0, hi = N_NODES;
    while (lo < hi) { int mid = (lo + hi) >> 1; if (batch[mid] < gph) lo = mid + 1; else hi = mid; }
    int s = lo;
    hi = N_NODES;
    while (lo < hi) { int mid = (lo + hi) >> 1; if (batch[mid] < gph + 1) lo = mid + 1; else hi = mid; }
    int c = lo - s;
    int d = t & 63, grp = t >> 6;
    float acc = 0.f;
    for (int i = grp; i < c; i += 4) acc += g_bufB[(s + i) * HID + d];
    sh[t] = acc;
    __syncthreads();
    if (t < 64) {
        float p = sh[t] + sh[64 + t] + sh[128 + t] + sh[192 + t];
        p *= 1.0f / fmaxf((float)c, 1.0f);
        sh[t] = p;
    }
    __syncthreads();
    if (t < 2) {
        float o = bl[t];
        #pragma unroll 8
        for (int dd = 0; dd < HID; dd++) o += sh[dd] * Wl[dd * 2 + t];
        outp[gph * 2 + t] = o;
    }
}

// ---------------- launch ---------------------------------------------------
extern "C" void kernel_launch(void* const* d_in, const int* in_sizes, int n_in,
                              void* d_out, int out_size) {
    const float* x     = (const float*)d_in[0];
    const int*   ei    = (const int*)d_in[1];    // int64 in reference -> int32 in harness
    const int*   batch = (const int*)d_in[2];
    const float* W1 = (const float*)d_in[3];
    const float* b1 = (const float*)d_in[4];
    const float* W2 = (const float*)d_in[5];
    const float* b2 = (const float*)d_in[6];
    const float* W3 = (const float*)d_in[7];
    const float* b3 = (const float*)d_in[8];
    const float* Wl = (const float*)d_in[9];
    const float* bl = (const float*)d_in[10];
    float* out = (float*)d_out;

    const int TB = 256;
    int nbE = (N_EDGES + TB - 1) / TB;                 // 4883
    int nbWarp = (N_NODES + 7) / 8;                    // 12500
    int nbTile = (N_NODES + 63) / 64;                  // 1563

    // CSR build + dinv + scaled input (3 launches)
    k_deg<<<nbE, TB>>>(ei);
    k_scan<<<SCAN_B, 256>>>(x);
    k_scatter<<<nbE, TB>>>(ei);

    // layer 1 (fp16 agg + GEMM + relu)
    k_l1<<<nbWarp, 256>>>(W1, b1);
    // layer 2
    k_xw64<<<nbTile, 128>>>(W2);
    k_aggh<<<nbWarp, 256>>>(b2, 1);
    // layer 3
    k_xw64<<<nbTile, 128>>>(W3);
    k_aggh<<<nbWarp, 256>>>(b3, 0);

    // pooling + classifier
    k_pool<<<NGRAPH, 256>>>(batch, Wl, bl, out);
}